// round 6
// baseline (speedup 1.0000x reference)
#include <cuda_runtime.h>
#include <cstdint>
#include <math_constants.h>

// Problem constants (fixed by the reference: M=4 molecules, N=2048 atoms)
#define NATOMS  2048
#define NMOL    4
#define NPAIRU  2096128u                        // N*(N-1)/2
#define MPU     (4u * NPAIRU)                   // 8,384,512  (6*MPU < 2^31)

// Output layout (flattened concat of the reference tuple, float32):
//   [0,     2*MP) : atom_index12 ([2, M*P] row-major, as float)
//   [2*MP,  5*MP) : shift_values ([M*P, 3], all zeros)   <- CE memset node
//   [5*MP,  6*MP) : mask         ([M*P], 1.0/0.0)

// Scratch: coords packed as float4 per atom, NaN-filled where species == -1.
__device__ float4 g_c4[NMOL * NATOMS];

__device__ __forceinline__ int row_offset(int i) {
    // offset of row i in triu_indices(N, k=1): i*(2N-1-i)/2
    return (i * (2 * NATOMS - 1 - i)) >> 1;
}

__global__ void prep_kernel(const int*   __restrict__ species,
                            const float* __restrict__ coords)
{
    const int a = blockIdx.x * blockDim.x + threadIdx.x;   // 0 .. NMOL*NATOMS-1
    float x = coords[3 * a + 0];
    float y = coords[3 * a + 1];
    float z = coords[3 * a + 2];
    if (species[a] == -1) { x = CUDART_NAN_F; y = CUDART_NAN_F; z = CUDART_NAN_F; }
    g_c4[a] = make_float4(x, y, z, 0.0f);
}

__global__ __launch_bounds__(256)
void fullpairwise_kernel(float* __restrict__ out)
{
    const int      m   = blockIdx.y;
    const unsigned tid = threadIdx.x;
    const unsigned p0  = blockIdx.x * 1024u + tid;   // pair id for k=0
    // grid.x = NPAIR/1024 = 2047 exactly -> no bounds checks

    const float4* __restrict__ cm = g_c4 + m * NATOMS;
    const float    cut2 = 5.2f * 5.2f;               // fp32, matches jnp
    const float    foff = (float)(m * NATOMS);
    const unsigned qm   = (unsigned)m * NPAIRU;

    // ---- invert triangular index ONCE (k=0): disc < 2^24, exact in fp32 ----
    const int pi0  = (int)p0;
    const int disc = 16769025 - 8 * pi0;             // 4095^2 - 8p
    int i = (int)((4095.0f - sqrtf((float)disc)) * 0.5f);
    if (i < 0) i = 0;
    while (row_offset(i + 1) <= pi0) ++i;
    while (row_offset(i) > pi0)      --i;
    int j = i + 1 + (pi0 - row_offset(i));

    // ---- 4 pairs per thread, 256 apart: coalesced loads & scalar stores ----
    #pragma unroll
    for (int k = 0; k < 4; ++k) {
        const float4 ci = __ldg(&cm[i]);   // warp-uniform-ish broadcast
        const float4 cj = __ldg(&cm[j]);   // lane-consecutive -> coalesced

        const float dx = ci.x - cj.x;
        const float dy = ci.y - cj.y;
        const float dz = ci.z - cj.z;
        // exact fp32, no FMA contraction, jnp reduction order ((x^2+y^2)+z^2);
        // NaN (padded atoms) compares false, matching the reference mask.
        const float d2 = __fadd_rn(__fadd_rn(__fmul_rn(dx, dx),
                                             __fmul_rn(dy, dy)),
                                   __fmul_rn(dz, dz));

        const unsigned q = qm + p0 + (unsigned)k * 256u;
        out[q]            = (float)i + foff;          // atom_index12 row 0
        out[MPU + q]      = (float)j + foff;          // atom_index12 row 1
        out[5u * MPU + q] = (d2 <= cut2) ? 1.f : 0.f; // mask

        // advance 256 pairs; dead (and elided) after the last iteration.
        if (k < 3) {
            j += 256;
            while (j >= NATOMS) { ++i; j = i + 1 + (j - NATOMS); }
        }
    }
}

extern "C" void kernel_launch(void* const* d_in, const int* in_sizes, int n_in,
                              void* d_out, int out_size)
{
    const int*   species = (const int*)  d_in[0];
    const float* coords  = (const float*)d_in[1];
    float*       out     = (float*)d_out;

    // Fork-join side stream (created once, outside capture on the first
    // correctness call; reused identically on every call -> deterministic).
    static cudaStream_t s2  = nullptr;
    static cudaEvent_t  evF = nullptr, evJ = nullptr;
    if (s2 == nullptr) {
        cudaStreamCreateWithFlags(&s2, cudaStreamNonBlocking);
        cudaEventCreateWithFlags(&evF, cudaEventDisableTiming);
        cudaEventCreateWithFlags(&evJ, cudaEventDisableTiming);
    }

    // Fork: zeros region (shift_values, 100.6MB) as a CE memset node running
    // concurrently with the SM kernels. 0x00 bytes == 0.0f.
    cudaEventRecord(evF, 0);
    cudaStreamWaitEvent(s2, evF, 0);
    cudaMemsetAsync(out + (size_t)2 * MPU, 0, (size_t)3 * MPU * sizeof(float), s2);

    // Main path on the default stream.
    prep_kernel<<<(NMOL * NATOMS) / 256, 256>>>(species, coords);
    dim3 grid(NPAIRU / 1024u, NMOL);   // (2047, 4), exact coverage
    fullpairwise_kernel<<<grid, 256>>>(out);

    // Join.
    cudaEventRecord(evJ, s2);
    cudaStreamWaitEvent(0, evJ, 0);
}